// round 16
// baseline (speedup 1.0000x reference)
#include <cuda_runtime.h>
#include <cuda_bf16.h>
#include <math.h>
#include <stdint.h>

#define NB  256
#define NT  512
#define NX  512
#define HB  (NB / 2)     // half batch

// ---------------------------------------------------------------------------
// Device scratch (static; no allocations anywhere)
// ---------------------------------------------------------------------------
__device__ __nv_bfloat16 g_phi_hi[(size_t)NB * NT * NX];
__device__ __nv_bfloat16 g_phi_lo[(size_t)NB * NT * NX];
__device__ __nv_bfloat16 g_wt_hi[(size_t)NX * NX];
__device__ __nv_bfloat16 g_wt_lo[(size_t)NX * NX];
__device__ int      g_T0[NB];
__device__ float    g_Wf[NX * NX];
__device__ unsigned g_bar;

// ---------------------------------------------------------------------------
// PTX helpers (sm_80-era, safe on compute_103)
// ---------------------------------------------------------------------------
__device__ __forceinline__ uint32_t smem_u32(const void* p) {
    uint32_t a;
    asm("{ .reg .u64 t; cvta.to.shared.u64 t, %1; cvt.u32.u64 %0, t; }" : "=r"(a) : "l"(p));
    return a;
}
__device__ __forceinline__ void cp_async16(uint32_t dst, const void* src) {
    asm volatile("cp.async.cg.shared.global [%0], [%1], 16;" :: "r"(dst), "l"(src) : "memory");
}
#define CP_COMMIT() asm volatile("cp.async.commit_group;" ::: "memory")

__device__ __forceinline__ void ldsm_x4(uint32_t* r, uint32_t addr) {
    asm volatile("ldmatrix.sync.aligned.m8n8.x4.shared.b16 {%0,%1,%2,%3}, [%4];"
        : "=r"(r[0]), "=r"(r[1]), "=r"(r[2]), "=r"(r[3]) : "r"(addr));
}
__device__ __forceinline__ void mma16816(float* c, const uint32_t* a, const uint32_t* b) {
    asm volatile("mma.sync.aligned.m16n8k16.row.col.f32.bf16.bf16.f32 "
        "{%0,%1,%2,%3}, {%4,%5,%6,%7}, {%8,%9}, {%0,%1,%2,%3};"
        : "+f"(c[0]), "+f"(c[1]), "+f"(c[2]), "+f"(c[3])
        : "r"(a[0]), "r"(a[1]), "r"(a[2]), "r"(a[3]), "r"(b[0]), "r"(b[1]));
}

// ---------------------------------------------------------------------------
// argmin -> T0 per sample
// ---------------------------------------------------------------------------
__global__ void argmin_kernel(const float* __restrict__ phi) {
    int b = blockIdx.x, lane = threadIdx.x;
    const float* p = phi + (size_t)b * NT * NX;
    float bv0 = 1e38f; int bi0 = 0;
    float bv1 = 1e38f; int bi1 = 0;
    for (int t = lane; t < NT; t += 32) {
        float v0 = fabsf(p[(size_t)t * NX + 0]);
        float v1 = fabsf(p[(size_t)t * NX + 1]);
        if (v0 < bv0) { bv0 = v0; bi0 = t; }
        if (v1 < bv1) { bv1 = v1; bi1 = t; }
    }
    #pragma unroll
    for (int o = 16; o; o >>= 1) {
        float ov = __shfl_down_sync(0xffffffffu, bv0, o);
        int   oi = __shfl_down_sync(0xffffffffu, bi0, o);
        if (ov < bv0 || (ov == bv0 && oi < bi0)) { bv0 = ov; bi0 = oi; }
        ov = __shfl_down_sync(0xffffffffu, bv1, o);
        oi = __shfl_down_sync(0xffffffffu, bi1, o);
        if (ov < bv1 || (ov == bv1 && oi < bi1)) { bv1 = ov; bi1 = oi; }
    }
    if (lane == 0) g_T0[b] = (bi0 > bi1) ? bi1 : bi0;
}

// ---------------------------------------------------------------------------
// W prep (main stream): transpose-split to bf16 hi/lo
// ---------------------------------------------------------------------------
__global__ void prep_W_bf16(const float* __restrict__ W) {
    __shared__ float t[32][33];
    int tx = threadIdx.x, ty = threadIdx.y;
    int r = blockIdx.y * 32 + ty, c = blockIdx.x * 32 + tx;
    t[ty][tx] = W[(size_t)r * NX + c];
    __syncthreads();
    int rr = blockIdx.x * 32 + ty, cc = blockIdx.y * 32 + tx;
    float v = t[tx][ty];
    __nv_bfloat16 hi = __float2bfloat16(v);
    __nv_bfloat16 lo = __float2bfloat16(v - __bfloat162float(hi));
    g_wt_hi[(size_t)rr * NX + cc] = hi;
    g_wt_lo[(size_t)rr * NX + cc] = lo;
}

// ---------------------------------------------------------------------------
// W prep (side stream): fp32 copy + barrier reset
// ---------------------------------------------------------------------------
__global__ void copy_Wf(const float* __restrict__ W) {
    int i = blockIdx.x * blockDim.x + threadIdx.x;
    if (i < NX * NX) g_Wf[i] = W[i];
    if (i == 0) g_bar = 0u;
}

// ---------------------------------------------------------------------------
// phi prep: roll along x by +T0 and split to bf16 hi/lo. Half-batch version:
// processes rows [b0*NT, (b0+HB)*NT).
// ---------------------------------------------------------------------------
__global__ void prep_phi_kernel(const float* __restrict__ phi, int b0) {
    int row = blockIdx.x + b0 * NT;
    int b = row >> 9;
    int T0 = g_T0[b];
    const float* src = phi + (size_t)row * NX;
    __nv_bfloat16* dh = g_phi_hi + (size_t)row * NX;
    __nv_bfloat16* dl = g_phi_lo + (size_t)row * NX;
    for (int u = threadIdx.x; u < NX; u += 128) {
        float f = src[(u - T0) & (NX - 1)];
        __nv_bfloat16 hi = __float2bfloat16(f);
        __nv_bfloat16 lo = __float2bfloat16(f - __bfloat162float(hi));
        dh[u] = hi; dl[u] = lo;
    }
}

// ---------------------------------------------------------------------------
// Single-kernel fp32 GENP LU (logdet only). 8 blocks x 512 threads, grid-wide
// spin barrier. (Unchanged from R15 — fully hidden under the main chain.)
// ---------------------------------------------------------------------------
#define LUB 8
#define LU_SMEM ((32 * 33 + 32 + 16 * 32 * 36) * 4)

__device__ __forceinline__ void grid_sync(unsigned* barnum, int tid) {
    __syncthreads();
    if (tid == 0) {
        unsigned target = (++(*barnum)) * LUB;
        __threadfence();
        atomicAdd(&g_bar, 1u);
        while (*((volatile unsigned*)&g_bar) < target) { }
        __threadfence();
    }
    __syncthreads();
}

__global__ void __launch_bounds__(512) lu_all(float* __restrict__ out_ld) {
    extern __shared__ float sm[];
    float (*sD)[33] = (float(*)[33])sm;
    float* uinv    = sm + 32 * 33;
    float* bufbase = sm + 32 * 33 + 32;

    const int tid  = threadIdx.x;
    const int bid  = blockIdx.x;
    const int wid  = tid >> 5;
    const int lane = tid & 31;
    unsigned barnum = 0;
    double logsum = 0.0;

    for (int s = 0; s < 15; s++) {
        const int k0 = s * 32;
        const int m  = 15 - s;

        if (wid == 0) {
            for (int r = 0; r < 32; r++)
                sD[r][lane] = g_Wf[(size_t)(k0 + r) * NX + k0 + lane];
            __syncwarp();
            for (int j = 0; j < 31; j++) {
                if (lane > j) {
                    float mf = sD[lane][j] / sD[j][j];
                    sD[lane][j] = mf;
                    for (int c = j + 1; c < 32; c++) sD[lane][c] -= mf * sD[j][c];
                }
                __syncwarp();
            }
            uinv[lane] = 1.0f / sD[lane][lane];
            if (bid == 0) {
                double lg = log(fabs((double)sD[lane][lane]));
                #pragma unroll
                for (int o = 16; o; o >>= 1) lg += __shfl_down_sync(0xffffffffu, lg, o);
                if (lane == 0) logsum += lg;
            }
        }
        __syncthreads();

        for (int u = bid * 16 + wid; u < 2 * m; u += 128) {
            if (u < m) {
                int col = k0 + 32 + u * 32 + lane;
                float v[32];
                #pragma unroll
                for (int i = 0; i < 32; i++) v[i] = g_Wf[(size_t)(k0 + i) * NX + col];
                #pragma unroll
                for (int i = 0; i < 32; i++) {
                    float vi = v[i];
                    #pragma unroll
                    for (int r = i + 1; r < 32; r++) v[r] -= sD[r][i] * vi;
                }
                #pragma unroll
                for (int i = 0; i < 32; i++) g_Wf[(size_t)(k0 + i) * NX + col] = v[i];
            } else {
                int r0 = k0 + 32 + (u - m) * 32;
                float* buf = bufbase + wid * (32 * 36);
                for (int r = 0; r < 32; r++)
                    buf[r * 36 + lane] = g_Wf[(size_t)(r0 + r) * NX + k0 + lane];
                __syncwarp();
                float x[32];
                #pragma unroll
                for (int i = 0; i < 32; i++) x[i] = buf[lane * 36 + i];
                #pragma unroll
                for (int i = 0; i < 32; i++) {
                    float xi = x[i] * uinv[i];
                    x[i] = xi;
                    #pragma unroll
                    for (int c = i + 1; c < 32; c++) x[c] -= xi * sD[i][c];
                }
                #pragma unroll
                for (int i = 0; i < 32; i++) buf[lane * 36 + i] = x[i];
                __syncwarp();
                for (int r = 0; r < 32; r++)
                    g_Wf[(size_t)(r0 + r) * NX + k0 + lane] = buf[r * 36 + lane];
            }
        }
        grid_sync(&barnum, tid);

        const int grp = tid >> 8;
        const int gt  = tid & 255;
        const int ntile = m * m;
        float* L = bufbase + (grp * 2 + 0) * (32 * 36);
        float* U = bufbase + (grp * 2 + 1) * (32 * 36);
        const int nrounds = (ntile + 15) / 16;
        for (int rd = 0; rd < nrounds; rd++) {
            int t = bid * 2 + grp + rd * 16;
            bool act = (t < ntile);
            int r0 = 0, c0 = 0;
            if (act) {
                int ti = t / m, tj = t % m;
                r0 = k0 + 32 + ti * 32;
                c0 = k0 + 32 + tj * 32;
                int row = gt >> 3, c4 = (gt & 7) * 4;
                *(float4*)&L[row * 36 + c4] =
                    *(const float4*)&g_Wf[(size_t)(r0 + row) * NX + k0 + c4];
                *(float4*)&U[row * 36 + c4] =
                    *(const float4*)&g_Wf[(size_t)(k0 + row) * NX + c0 + c4];
            }
            __syncthreads();
            if (act) {
                int r = gt >> 3, c = (gt & 7) * 4;
                float a0 = 0, a1 = 0, a2 = 0, a3 = 0;
                #pragma unroll
                for (int k = 0; k < 32; k++) {
                    float l = L[r * 36 + k];
                    a0 += l * U[k * 36 + c + 0];
                    a1 += l * U[k * 36 + c + 1];
                    a2 += l * U[k * 36 + c + 2];
                    a3 += l * U[k * 36 + c + 3];
                }
                float4* dst = (float4*)&g_Wf[(size_t)(r0 + r) * NX + c0 + c];
                float4 o = *dst;
                o.x -= a0; o.y -= a1; o.z -= a2; o.w -= a3;
                *dst = o;
            }
            __syncthreads();
        }
        grid_sync(&barnum, tid);
    }

    if (bid == 0) {
        if (wid == 0) {
            const int k0 = 480;
            for (int r = 0; r < 32; r++)
                sD[r][lane] = g_Wf[(size_t)(k0 + r) * NX + k0 + lane];
            __syncwarp();
            for (int j = 0; j < 31; j++) {
                if (lane > j) {
                    float mf = sD[lane][j] / sD[j][j];
                    for (int c = j + 1; c < 32; c++) sD[lane][c] -= mf * sD[j][c];
                }
                __syncwarp();
            }
            double lg = log(fabs((double)sD[lane][lane]));
            #pragma unroll
            for (int o = 16; o; o >>= 1) lg += __shfl_down_sync(0xffffffffu, lg, o);
            if (lane == 0) uinv[0] = (float)((double)NT * (logsum + lg));
        }
        __syncthreads();
        float v = uinv[0];
        if (tid < NB) out_ld[tid] = v;
    }
}

// ---------------------------------------------------------------------------
// HMMA bf16 GEMM (half batch per launch), K = 3*512 concatenated.
// Tile 128x128, 8 warps, BK=64, 3-stage cp.async pipeline, one barrier/iter,
// fused output roll. b = blockIdx.z + b0.
// ---------------------------------------------------------------------------
#define BM 128
#define BN 128
#define SROW 144
#define STAGE_BYTES (128 * SROW)
#define NSTAGE 3
#define G_SMEM (2 * NSTAGE * STAGE_BYTES)
#define NITER 24

__global__ void __launch_bounds__(256, 2)
gemm_tc_kernel(float* __restrict__ out, int b0) {
    extern __shared__ __align__(16) char smem[];

    const int tid  = threadIdx.x;
    const int lane = tid & 31;
    const int wid  = tid >> 5;
    const int wr   = wid >> 2;
    const int wc   = wid & 3;

    const int b  = blockIdx.z + b0;
    const int n0 = blockIdx.x * BN;
    const int m0 = blockIdx.y * BM;
    const int T0 = g_T0[b];

    const uint32_t sAu = smem_u32(smem);
    const uint32_t sBu = sAu + NSTAGE * STAGE_BYTES;

    const char* aP[3];
    const char* bP[3];
    {
        const char* ph = (const char*)(g_phi_hi + (size_t)b * NT * NX);
        const char* pl = (const char*)(g_phi_lo + (size_t)b * NT * NX);
        aP[0] = ph; aP[1] = ph; aP[2] = pl;
        bP[0] = (const char*)g_wt_hi; bP[1] = (const char*)g_wt_lo; bP[2] = (const char*)g_wt_hi;
    }

    auto load_iter = [&](int it) {
        int p = it >> 3, c = it & 7, s = it % NSTAGE;
        size_t kofs = (size_t)c * 128;
        const char* asrc = aP[p];
        const char* bsrc = bP[p];
        #pragma unroll
        for (int rep = 0; rep < 4; rep++) {
            int idx = tid + rep * 256;
            int row = idx >> 3;
            int q   = idx & 7;
            uint32_t dofs = (uint32_t)(row * SROW + q * 16);
            cp_async16(sAu + s * STAGE_BYTES + dofs,
                       asrc + (size_t)(m0 + row) * 1024 + kofs + q * 16);
            cp_async16(sBu + s * STAGE_BYTES + dofs,
                       bsrc + (size_t)(n0 + row) * 1024 + kofs + q * 16);
        }
        CP_COMMIT();
    };

    float acc[4][4][4];
    #pragma unroll
    for (int i = 0; i < 4; i++)
        #pragma unroll
        for (int j = 0; j < 4; j++)
            #pragma unroll
            for (int q = 0; q < 4; q++) acc[i][j][q] = 0.0f;

    const int lm  = lane & 15;
    const int lk8 = lane >> 4;
    const int bn  = (lane & 7) + ((lane >> 4) << 3);
    const int bk8 = (lane >> 3) & 1;

    const uint32_t aLaneOfs = (uint32_t)((wr * 64 + lm) * SROW + lk8 * 16);
    const uint32_t bLaneOfs = (uint32_t)((wc * 32 + bn) * SROW + bk8 * 16);

    load_iter(0);
    load_iter(1);

    for (int it = 0; it < NITER; it++) {
        int s = it % NSTAGE;
        if (it == NITER - 1) {
            asm volatile("cp.async.wait_group 0;" ::: "memory");
        } else {
            asm volatile("cp.async.wait_group 1;" ::: "memory");
        }
        __syncthreads();

        if (it + 2 < NITER) load_iter(it + 2);

        const uint32_t aStage = sAu + s * STAGE_BYTES + aLaneOfs;
        const uint32_t bStage = sBu + s * STAGE_BYTES + bLaneOfs;

        #pragma unroll
        for (int ks = 0; ks < 4; ks++) {
            uint32_t af[4][4];
            #pragma unroll
            for (int i = 0; i < 4; i++)
                ldsm_x4(af[i], aStage + i * (16 * SROW) + ks * 32);
            uint32_t bf[2][4];
            #pragma unroll
            for (int jp = 0; jp < 2; jp++)
                ldsm_x4(bf[jp], bStage + jp * (16 * SROW) + ks * 32);
            #pragma unroll
            for (int i = 0; i < 4; i++)
                #pragma unroll
                for (int j = 0; j < 4; j++)
                    mma16816(acc[i][j], af[i], &bf[j >> 1][(j & 1) * 2]);
        }
    }

    float* C = out + (size_t)b * NT * NX;
    #pragma unroll
    for (int i = 0; i < 4; i++) {
        int m_lo = m0 + wr * 64 + i * 16 + (lane >> 2);
        int m_hi = m_lo + 8;
        int or_lo = (m_lo - T0 + NT) & (NT - 1);
        int or_hi = (m_hi - T0 + NT) & (NT - 1);
        #pragma unroll
        for (int j = 0; j < 4; j++) {
            int col = n0 + wc * 32 + j * 8 + (lane & 3) * 2;
            *(float2*)(C + (size_t)or_lo * NX + col) = make_float2(acc[i][j][0], acc[i][j][1]);
            *(float2*)(C + (size_t)or_hi * NX + col) = make_float2(acc[i][j][2], acc[i][j][3]);
        }
    }
}

// ---------------------------------------------------------------------------
// Launch. Batch split in halves to pipeline prep_phi against the GEMM:
//   stream0: argmin(0) -> prep_W(1) -> prep_phi_h0(2) -> GEMM_h0(3, profiled)
//            -> [wait e_pre] -> GEMM_h1
//   s_pre:   [wait e_arg] prep_phi_h1  (overlaps GEMM_h0's tail waves)
//   s_side:  copy_Wf -> lu_all  (logdet, joined at end)
// ---------------------------------------------------------------------------
extern "C" void kernel_launch(void* const* d_in, const int* in_sizes, int n_in,
                              void* d_out, int out_size) {
    const float* phi = (const float*)d_in[0];
    const float* W   = (const float*)d_in[1];
    float* out = (float*)d_out;

    static cudaStream_t s_side = nullptr, s_pre = nullptr;
    static cudaEvent_t  e_fork = nullptr, e_join = nullptr, e_arg = nullptr, e_pre = nullptr;
    if (s_side == nullptr) {
        cudaStreamCreateWithFlags(&s_side, cudaStreamNonBlocking);
        cudaStreamCreateWithFlags(&s_pre,  cudaStreamNonBlocking);
        cudaEventCreateWithFlags(&e_fork, cudaEventDisableTiming);
        cudaEventCreateWithFlags(&e_join, cudaEventDisableTiming);
        cudaEventCreateWithFlags(&e_arg,  cudaEventDisableTiming);
        cudaEventCreateWithFlags(&e_pre,  cudaEventDisableTiming);
        cudaFuncSetAttribute(gemm_tc_kernel,
                             cudaFuncAttributeMaxDynamicSharedMemorySize, G_SMEM);
        cudaFuncSetAttribute(lu_all,
                             cudaFuncAttributeMaxDynamicSharedMemorySize, LU_SMEM);
    }

    cudaEventRecord(e_fork, 0);
    cudaStreamWaitEvent(s_side, e_fork, 0);
    cudaStreamWaitEvent(s_pre,  e_fork, 0);

    // ---- main stream ----
    argmin_kernel<<<NB, 32>>>(phi);                          // launch 0
    cudaEventRecord(e_arg, 0);
    {
        dim3 g(NX / 32, NX / 32), blk(32, 32);
        prep_W_bf16<<<g, blk>>>(W);                          // launch 1
    }
    prep_phi_kernel<<<HB * NT, 128>>>(phi, 0);               // launch 2 (half 0)
    {
        dim3 grid(NX / BN, NT / BM, HB);
        gemm_tc_kernel<<<grid, 256, G_SMEM>>>(out, 0);       // launch 3 (profiled)
    }

    // ---- prep stream: second half of phi prep, overlapped with GEMM h0 ----
    cudaStreamWaitEvent(s_pre, e_arg, 0);
    prep_phi_kernel<<<HB * NT, 128, 0, s_pre>>>(phi, HB);
    cudaEventRecord(e_pre, s_pre);

    // ---- main stream: second-half GEMM ----
    cudaStreamWaitEvent(0, e_pre, 0);
    {
        dim3 grid(NX / BN, NT / BM, HB);
        gemm_tc_kernel<<<grid, 256, G_SMEM>>>(out, HB);
    }

    // ---- side stream: fp32 logdet, 2 nodes ----
    copy_Wf<<<(NX * NX + 255) / 256, 256, 0, s_side>>>(W);
    lu_all<<<LUB, 512, LU_SMEM, s_side>>>(out + (out_size - NB));

    cudaEventRecord(e_join, s_side);
    cudaStreamWaitEvent(0, e_join, 0);
}

// round 17
// speedup vs baseline: 1.1340x; 1.1340x over previous
#include <cuda_runtime.h>
#include <cuda_bf16.h>
#include <math.h>
#include <stdint.h>

#define NB  256
#define NT  512
#define NX  512

// ---------------------------------------------------------------------------
// Device scratch (static; no allocations anywhere)
// ---------------------------------------------------------------------------
__device__ __nv_bfloat16 g_phi_hi[(size_t)NB * NT * NX];
__device__ __nv_bfloat16 g_phi_lo[(size_t)NB * NT * NX];
__device__ __nv_bfloat16 g_wt_hi[(size_t)NX * NX];
__device__ __nv_bfloat16 g_wt_lo[(size_t)NX * NX];
__device__ int      g_T0[NB];
__device__ float    g_Wf[NX * NX];
__device__ unsigned g_bar;

// ---------------------------------------------------------------------------
// PTX helpers (sm_80-era, safe on compute_103)
// ---------------------------------------------------------------------------
__device__ __forceinline__ uint32_t smem_u32(const void* p) {
    uint32_t a;
    asm("{ .reg .u64 t; cvta.to.shared.u64 t, %1; cvt.u32.u64 %0, t; }" : "=r"(a) : "l"(p));
    return a;
}
__device__ __forceinline__ void cp_async16(uint32_t dst, const void* src) {
    asm volatile("cp.async.cg.shared.global [%0], [%1], 16;" :: "r"(dst), "l"(src) : "memory");
}
#define CP_COMMIT() asm volatile("cp.async.commit_group;" ::: "memory")

__device__ __forceinline__ void ldsm_x4(uint32_t* r, uint32_t addr) {
    asm volatile("ldmatrix.sync.aligned.m8n8.x4.shared.b16 {%0,%1,%2,%3}, [%4];"
        : "=r"(r[0]), "=r"(r[1]), "=r"(r[2]), "=r"(r[3]) : "r"(addr));
}
__device__ __forceinline__ void mma16816(float* c, const uint32_t* a, const uint32_t* b) {
    asm volatile("mma.sync.aligned.m16n8k16.row.col.f32.bf16.bf16.f32 "
        "{%0,%1,%2,%3}, {%4,%5,%6,%7}, {%8,%9}, {%0,%1,%2,%3};"
        : "+f"(c[0]), "+f"(c[1]), "+f"(c[2]), "+f"(c[3])
        : "r"(a[0]), "r"(a[1]), "r"(a[2]), "r"(a[3]), "r"(b[0]), "r"(b[1]));
}

// ---------------------------------------------------------------------------
// argmin -> T0 per sample
// ---------------------------------------------------------------------------
__global__ void argmin_kernel(const float* __restrict__ phi) {
    int b = blockIdx.x, lane = threadIdx.x;
    const float* p = phi + (size_t)b * NT * NX;
    float bv0 = 1e38f; int bi0 = 0;
    float bv1 = 1e38f; int bi1 = 0;
    for (int t = lane; t < NT; t += 32) {
        float v0 = fabsf(p[(size_t)t * NX + 0]);
        float v1 = fabsf(p[(size_t)t * NX + 1]);
        if (v0 < bv0) { bv0 = v0; bi0 = t; }
        if (v1 < bv1) { bv1 = v1; bi1 = t; }
    }
    #pragma unroll
    for (int o = 16; o; o >>= 1) {
        float ov = __shfl_down_sync(0xffffffffu, bv0, o);
        int   oi = __shfl_down_sync(0xffffffffu, bi0, o);
        if (ov < bv0 || (ov == bv0 && oi < bi0)) { bv0 = ov; bi0 = oi; }
        ov = __shfl_down_sync(0xffffffffu, bv1, o);
        oi = __shfl_down_sync(0xffffffffu, bi1, o);
        if (ov < bv1 || (ov == bv1 && oi < bi1)) { bv1 = ov; bi1 = oi; }
    }
    if (lane == 0) g_T0[b] = (bi0 > bi1) ? bi1 : bi0;
}

// ---------------------------------------------------------------------------
// W prep (main stream): transpose-split to bf16 hi/lo
// ---------------------------------------------------------------------------
__global__ void prep_W_bf16(const float* __restrict__ W) {
    __shared__ float t[32][33];
    int tx = threadIdx.x, ty = threadIdx.y;
    int r = blockIdx.y * 32 + ty, c = blockIdx.x * 32 + tx;
    t[ty][tx] = W[(size_t)r * NX + c];
    __syncthreads();
    int rr = blockIdx.x * 32 + ty, cc = blockIdx.y * 32 + tx;
    float v = t[tx][ty];
    __nv_bfloat16 hi = __float2bfloat16(v);
    __nv_bfloat16 lo = __float2bfloat16(v - __bfloat162float(hi));
    g_wt_hi[(size_t)rr * NX + cc] = hi;
    g_wt_lo[(size_t)rr * NX + cc] = lo;
}

// ---------------------------------------------------------------------------
// W prep (side stream): fp32 copy + barrier reset
// ---------------------------------------------------------------------------
__global__ void copy_Wf(const float* __restrict__ W) {
    int i = blockIdx.x * blockDim.x + threadIdx.x;
    if (i < NX * NX) g_Wf[i] = W[i];
    if (i == 0) g_bar = 0u;
}

// ---------------------------------------------------------------------------
// phi prep: roll along x by +T0 and split to bf16 hi/lo.
// 8192 blocks x 256 threads, 16 rows per block (looped, 2 rows in flight),
// bf16x2 stores. Cuts block-dispatch overhead ~16x vs one-row-per-block.
// ---------------------------------------------------------------------------
#define PREP_ROWS 16

__global__ void __launch_bounds__(256) prep_phi_kernel(const float* __restrict__ phi) {
    const int row0 = blockIdx.x * PREP_ROWS;
    const int half = threadIdx.x >> 7;          // 0..1: which of 2 concurrent rows
    const int l128 = threadIdx.x & 127;

    #pragma unroll
    for (int r = 0; r < PREP_ROWS; r += 2) {
        int row = row0 + r + half;
        int b = row >> 9;
        int T0 = g_T0[b];
        const float* src = phi + (size_t)row * NX;
        __nv_bfloat16* dh = g_phi_hi + (size_t)row * NX;
        __nv_bfloat16* dl = g_phi_lo + (size_t)row * NX;
        #pragma unroll
        for (int k = 0; k < 2; k++) {
            int u = l128 * 2 + k * 256;          // even element index
            float f0 = src[(u     - T0) & (NX - 1)];
            float f1 = src[(u + 1 - T0) & (NX - 1)];
            __nv_bfloat16 h0 = __float2bfloat16(f0);
            __nv_bfloat16 h1 = __float2bfloat16(f1);
            __nv_bfloat16 l0 = __float2bfloat16(f0 - __bfloat162float(h0));
            __nv_bfloat16 l1 = __float2bfloat16(f1 - __bfloat162float(h1));
            __nv_bfloat162 hv; hv.x = h0; hv.y = h1;
            __nv_bfloat162 lv; lv.x = l0; lv.y = l1;
            *(__nv_bfloat162*)(dh + u) = hv;
            *(__nv_bfloat162*)(dl + u) = lv;
        }
    }
}

// ---------------------------------------------------------------------------
// Single-kernel fp32 GENP LU (logdet only). 8 blocks x 512 threads, grid-wide
// spin barrier. (Unchanged — fully hidden under the main chain.)
// ---------------------------------------------------------------------------
#define LUB 8
#define LU_SMEM ((32 * 33 + 32 + 16 * 32 * 36) * 4)

__device__ __forceinline__ void grid_sync(unsigned* barnum, int tid) {
    __syncthreads();
    if (tid == 0) {
        unsigned target = (++(*barnum)) * LUB;
        __threadfence();
        atomicAdd(&g_bar, 1u);
        while (*((volatile unsigned*)&g_bar) < target) { }
        __threadfence();
    }
    __syncthreads();
}

__global__ void __launch_bounds__(512) lu_all(float* __restrict__ out_ld) {
    extern __shared__ float sm[];
    float (*sD)[33] = (float(*)[33])sm;
    float* uinv    = sm + 32 * 33;
    float* bufbase = sm + 32 * 33 + 32;

    const int tid  = threadIdx.x;
    const int bid  = blockIdx.x;
    const int wid  = tid >> 5;
    const int lane = tid & 31;
    unsigned barnum = 0;
    double logsum = 0.0;

    for (int s = 0; s < 15; s++) {
        const int k0 = s * 32;
        const int m  = 15 - s;

        if (wid == 0) {
            for (int r = 0; r < 32; r++)
                sD[r][lane] = g_Wf[(size_t)(k0 + r) * NX + k0 + lane];
            __syncwarp();
            for (int j = 0; j < 31; j++) {
                if (lane > j) {
                    float mf = sD[lane][j] / sD[j][j];
                    sD[lane][j] = mf;
                    for (int c = j + 1; c < 32; c++) sD[lane][c] -= mf * sD[j][c];
                }
                __syncwarp();
            }
            uinv[lane] = 1.0f / sD[lane][lane];
            if (bid == 0) {
                double lg = log(fabs((double)sD[lane][lane]));
                #pragma unroll
                for (int o = 16; o; o >>= 1) lg += __shfl_down_sync(0xffffffffu, lg, o);
                if (lane == 0) logsum += lg;
            }
        }
        __syncthreads();

        for (int u = bid * 16 + wid; u < 2 * m; u += 128) {
            if (u < m) {
                int col = k0 + 32 + u * 32 + lane;
                float v[32];
                #pragma unroll
                for (int i = 0; i < 32; i++) v[i] = g_Wf[(size_t)(k0 + i) * NX + col];
                #pragma unroll
                for (int i = 0; i < 32; i++) {
                    float vi = v[i];
                    #pragma unroll
                    for (int r = i + 1; r < 32; r++) v[r] -= sD[r][i] * vi;
                }
                #pragma unroll
                for (int i = 0; i < 32; i++) g_Wf[(size_t)(k0 + i) * NX + col] = v[i];
            } else {
                int r0 = k0 + 32 + (u - m) * 32;
                float* buf = bufbase + wid * (32 * 36);
                for (int r = 0; r < 32; r++)
                    buf[r * 36 + lane] = g_Wf[(size_t)(r0 + r) * NX + k0 + lane];
                __syncwarp();
                float x[32];
                #pragma unroll
                for (int i = 0; i < 32; i++) x[i] = buf[lane * 36 + i];
                #pragma unroll
                for (int i = 0; i < 32; i++) {
                    float xi = x[i] * uinv[i];
                    x[i] = xi;
                    #pragma unroll
                    for (int c = i + 1; c < 32; c++) x[c] -= xi * sD[i][c];
                }
                #pragma unroll
                for (int i = 0; i < 32; i++) buf[lane * 36 + i] = x[i];
                __syncwarp();
                for (int r = 0; r < 32; r++)
                    g_Wf[(size_t)(r0 + r) * NX + k0 + lane] = buf[r * 36 + lane];
            }
        }
        grid_sync(&barnum, tid);

        const int grp = tid >> 8;
        const int gt  = tid & 255;
        const int ntile = m * m;
        float* L = bufbase + (grp * 2 + 0) * (32 * 36);
        float* U = bufbase + (grp * 2 + 1) * (32 * 36);
        const int nrounds = (ntile + 15) / 16;
        for (int rd = 0; rd < nrounds; rd++) {
            int t = bid * 2 + grp + rd * 16;
            bool act = (t < ntile);
            int r0 = 0, c0 = 0;
            if (act) {
                int ti = t / m, tj = t % m;
                r0 = k0 + 32 + ti * 32;
                c0 = k0 + 32 + tj * 32;
                int row = gt >> 3, c4 = (gt & 7) * 4;
                *(float4*)&L[row * 36 + c4] =
                    *(const float4*)&g_Wf[(size_t)(r0 + row) * NX + k0 + c4];
                *(float4*)&U[row * 36 + c4] =
                    *(const float4*)&g_Wf[(size_t)(k0 + row) * NX + c0 + c4];
            }
            __syncthreads();
            if (act) {
                int r = gt >> 3, c = (gt & 7) * 4;
                float a0 = 0, a1 = 0, a2 = 0, a3 = 0;
                #pragma unroll
                for (int k = 0; k < 32; k++) {
                    float l = L[r * 36 + k];
                    a0 += l * U[k * 36 + c + 0];
                    a1 += l * U[k * 36 + c + 1];
                    a2 += l * U[k * 36 + c + 2];
                    a3 += l * U[k * 36 + c + 3];
                }
                float4* dst = (float4*)&g_Wf[(size_t)(r0 + r) * NX + c0 + c];
                float4 o = *dst;
                o.x -= a0; o.y -= a1; o.z -= a2; o.w -= a3;
                *dst = o;
            }
            __syncthreads();
        }
        grid_sync(&barnum, tid);
    }

    if (bid == 0) {
        if (wid == 0) {
            const int k0 = 480;
            for (int r = 0; r < 32; r++)
                sD[r][lane] = g_Wf[(size_t)(k0 + r) * NX + k0 + lane];
            __syncwarp();
            for (int j = 0; j < 31; j++) {
                if (lane > j) {
                    float mf = sD[lane][j] / sD[j][j];
                    for (int c = j + 1; c < 32; c++) sD[lane][c] -= mf * sD[j][c];
                }
                __syncwarp();
            }
            double lg = log(fabs((double)sD[lane][lane]));
            #pragma unroll
            for (int o = 16; o; o >>= 1) lg += __shfl_down_sync(0xffffffffu, lg, o);
            if (lane == 0) uinv[0] = (float)((double)NT * (logsum + lg));
        }
        __syncthreads();
        float v = uinv[0];
        if (tid < NB) out_ld[tid] = v;
    }
}

// ---------------------------------------------------------------------------
// HMMA bf16 GEMM (full batch), K = 3*512 concatenated (hi*hi, hi*lo, lo*hi).
// Tile 128x128, 8 warps, BK=64, 3-stage cp.async pipeline, one barrier/iter,
// fused output roll. (R15 config — best measured.)
// ---------------------------------------------------------------------------
#define BM 128
#define BN 128
#define SROW 144
#define STAGE_BYTES (128 * SROW)
#define NSTAGE 3
#define G_SMEM (2 * NSTAGE * STAGE_BYTES)
#define NITER 24

__global__ void __launch_bounds__(256, 2)
gemm_tc_kernel(float* __restrict__ out) {
    extern __shared__ __align__(16) char smem[];

    const int tid  = threadIdx.x;
    const int lane = tid & 31;
    const int wid  = tid >> 5;
    const int wr   = wid >> 2;
    const int wc   = wid & 3;

    const int b  = blockIdx.z;
    const int n0 = blockIdx.x * BN;
    const int m0 = blockIdx.y * BM;
    const int T0 = g_T0[b];

    const uint32_t sAu = smem_u32(smem);
    const uint32_t sBu = sAu + NSTAGE * STAGE_BYTES;

    const char* aP[3];
    const char* bP[3];
    {
        const char* ph = (const char*)(g_phi_hi + (size_t)b * NT * NX);
        const char* pl = (const char*)(g_phi_lo + (size_t)b * NT * NX);
        aP[0] = ph; aP[1] = ph; aP[2] = pl;
        bP[0] = (const char*)g_wt_hi; bP[1] = (const char*)g_wt_lo; bP[2] = (const char*)g_wt_hi;
    }

    auto load_iter = [&](int it) {
        int p = it >> 3, c = it & 7, s = it % NSTAGE;
        size_t kofs = (size_t)c * 128;
        const char* asrc = aP[p];
        const char* bsrc = bP[p];
        #pragma unroll
        for (int rep = 0; rep < 4; rep++) {
            int idx = tid + rep * 256;
            int row = idx >> 3;
            int q   = idx & 7;
            uint32_t dofs = (uint32_t)(row * SROW + q * 16);
            cp_async16(sAu + s * STAGE_BYTES + dofs,
                       asrc + (size_t)(m0 + row) * 1024 + kofs + q * 16);
            cp_async16(sBu + s * STAGE_BYTES + dofs,
                       bsrc + (size_t)(n0 + row) * 1024 + kofs + q * 16);
        }
        CP_COMMIT();
    };

    float acc[4][4][4];
    #pragma unroll
    for (int i = 0; i < 4; i++)
        #pragma unroll
        for (int j = 0; j < 4; j++)
            #pragma unroll
            for (int q = 0; q < 4; q++) acc[i][j][q] = 0.0f;

    const int lm  = lane & 15;
    const int lk8 = lane >> 4;
    const int bn  = (lane & 7) + ((lane >> 4) << 3);
    const int bk8 = (lane >> 3) & 1;

    const uint32_t aLaneOfs = (uint32_t)((wr * 64 + lm) * SROW + lk8 * 16);
    const uint32_t bLaneOfs = (uint32_t)((wc * 32 + bn) * SROW + bk8 * 16);

    load_iter(0);
    load_iter(1);

    for (int it = 0; it < NITER; it++) {
        int s = it % NSTAGE;
        if (it == NITER - 1) {
            asm volatile("cp.async.wait_group 0;" ::: "memory");
        } else {
            asm volatile("cp.async.wait_group 1;" ::: "memory");
        }
        __syncthreads();

        if (it + 2 < NITER) load_iter(it + 2);

        const uint32_t aStage = sAu + s * STAGE_BYTES + aLaneOfs;
        const uint32_t bStage = sBu + s * STAGE_BYTES + bLaneOfs;

        #pragma unroll
        for (int ks = 0; ks < 4; ks++) {
            uint32_t af[4][4];
            #pragma unroll
            for (int i = 0; i < 4; i++)
                ldsm_x4(af[i], aStage + i * (16 * SROW) + ks * 32);
            uint32_t bf[2][4];
            #pragma unroll
            for (int jp = 0; jp < 2; jp++)
                ldsm_x4(bf[jp], bStage + jp * (16 * SROW) + ks * 32);
            #pragma unroll
            for (int i = 0; i < 4; i++)
                #pragma unroll
                for (int j = 0; j < 4; j++)
                    mma16816(acc[i][j], af[i], &bf[j >> 1][(j & 1) * 2]);
        }
    }

    float* C = out + (size_t)b * NT * NX;
    #pragma unroll
    for (int i = 0; i < 4; i++) {
        int m_lo = m0 + wr * 64 + i * 16 + (lane >> 2);
        int m_hi = m_lo + 8;
        int or_lo = (m_lo - T0 + NT) & (NT - 1);
        int or_hi = (m_hi - T0 + NT) & (NT - 1);
        #pragma unroll
        for (int j = 0; j < 4; j++) {
            int col = n0 + wc * 32 + j * 8 + (lane & 3) * 2;
            *(float2*)(C + (size_t)or_lo * NX + col) = make_float2(acc[i][j][0], acc[i][j][1]);
            *(float2*)(C + (size_t)or_hi * NX + col) = make_float2(acc[i][j][2], acc[i][j][3]);
        }
    }
}

// ---------------------------------------------------------------------------
// Launch (R15 structure). Main: argmin(0), prep_W(1), prep_phi(2),
// GEMM(3 <- ncu target). Side: copy_Wf + lu_all.
// ---------------------------------------------------------------------------
extern "C" void kernel_launch(void* const* d_in, const int* in_sizes, int n_in,
                              void* d_out, int out_size) {
    const float* phi = (const float*)d_in[0];
    const float* W   = (const float*)d_in[1];
    float* out = (float*)d_out;

    static cudaStream_t s_side = nullptr;
    static cudaEvent_t  e_fork = nullptr, e_join = nullptr;
    if (s_side == nullptr) {
        cudaStreamCreateWithFlags(&s_side, cudaStreamNonBlocking);
        cudaEventCreateWithFlags(&e_fork, cudaEventDisableTiming);
        cudaEventCreateWithFlags(&e_join, cudaEventDisableTiming);
        cudaFuncSetAttribute(gemm_tc_kernel,
                             cudaFuncAttributeMaxDynamicSharedMemorySize, G_SMEM);
        cudaFuncSetAttribute(lu_all,
                             cudaFuncAttributeMaxDynamicSharedMemorySize, LU_SMEM);
    }

    cudaEventRecord(e_fork, 0);
    cudaStreamWaitEvent(s_side, e_fork, 0);

    // ---- main stream ----
    argmin_kernel<<<NB, 32>>>(phi);                          // launch 0
    {
        dim3 g(NX / 32, NX / 32), blk(32, 32);
        prep_W_bf16<<<g, blk>>>(W);                          // launch 1
    }
    prep_phi_kernel<<<NB * NT / PREP_ROWS, 256>>>(phi);      // launch 2
    {
        dim3 grid(NX / BN, NT / BM, NB);
        gemm_tc_kernel<<<grid, 256, G_SMEM>>>(out);          // launch 3 (profiled)
    }

    // ---- side stream: fp32 logdet, 2 nodes ----
    copy_Wf<<<(NX * NX + 255) / 256, 256, 0, s_side>>>(W);
    lu_all<<<LUB, 512, LU_SMEM, s_side>>>(out + (out_size - NB));

    cudaEventRecord(e_join, s_side);
    cudaStreamWaitEvent(0, e_join, 0);
}